// round 1
// baseline (speedup 1.0000x reference)
#include <cuda_runtime.h>
#include <math.h>

#define L_ 6
#define H_ 16
#define N_ 2048
#define DM_ 1024
#define DK_ 64
#define DV_ 64
#define DFF_ 4096

// ---------------- scratch (static device globals; no allocation) ----------------
__device__ float g_h[N_ * DM_];
__device__ float g_Q[H_ * N_ * DK_];
__device__ float g_K[H_ * N_ * DK_];
__device__ float g_V[H_ * N_ * DV_];
__device__ float g_lse[H_ * N_];
__device__ float g_KtV[H_ * DK_ * DV_];
__device__ float g_lseV[H_ * DV_];
__device__ float g_attn[N_ * DM_];
__device__ float g_Z[N_ * DM_];
__device__ float g_h2[N_ * DM_];
__device__ float g_F1[N_ * DFF_];
__device__ float g_R[N_ * DM_];

// ---------------- embedding + positional encoding ----------------
__global__ void embed_kernel(const int* __restrict__ X, const float* __restrict__ emb,
                             float* __restrict__ h) {
    int n = blockIdx.x;
    int t = threadIdx.x;
    const float* e = emb + (size_t)X[n] * DM_;
    float pos = (float)(n + 1);
#pragma unroll
    for (int k = 0; k < 2; k++) {
        int i = t + k * 256;  // pair index, < 512
        float a = (float)(2 * i) / (float)DM_ * -9.210340371976184f;
        float f = expf(a);
        float tt = pos * f;
        h[(size_t)n * DM_ + 2 * i]     = e[2 * i]     + sinf(tt);
        h[(size_t)n * DM_ + 2 * i + 1] = e[2 * i + 1] + cosf(tt);
    }
}

// ---------------- generic batched SGEMM: C = alpha*A@B + bias - colsub, optional relu ----
// A[M,Kd] lda, B[Kd,Nc] ldb, C[M,Nc] ldc. BM=128 BN=64 BK=16, 256 threads, 8x4 micro.
template <bool RELU>
__global__ void __launch_bounds__(256) sgemm_kernel(
    const float* __restrict__ A, const float* __restrict__ B, float* __restrict__ C,
    const float* __restrict__ bias, const float* __restrict__ colsub,
    int M, int Nc, int Kd, int lda, int ldb, int ldc,
    long sA, long sB, long sC, long sBias, long sSub, float alpha) {
    __shared__ float As[16][132];
    __shared__ float Bs[16][64];

    int b = blockIdx.z;
    A += (size_t)b * sA;
    B += (size_t)b * sB;
    C += (size_t)b * sC;
    if (bias) bias += (size_t)b * sBias;
    if (colsub) colsub += (size_t)b * sSub;

    int bm0 = blockIdx.y * 128;
    int bn0 = blockIdx.x * 64;
    int t = threadIdx.x;
    int row0 = (t >> 4) * 8;
    int col0 = (t & 15) * 4;

    float acc[8][4];
#pragma unroll
    for (int i = 0; i < 8; i++)
#pragma unroll
        for (int j = 0; j < 4; j++) acc[i][j] = 0.f;

    for (int kt = 0; kt < Kd; kt += 16) {
        // load A tile (transposed into smem)
#pragma unroll
        for (int r = 0; r < 2; r++) {
            int f = t + 256 * r;
            int m = f >> 2, k4 = f & 3;
            float4 av = *(const float4*)(A + (size_t)(bm0 + m) * lda + kt + k4 * 4);
            As[k4 * 4 + 0][m] = av.x;
            As[k4 * 4 + 1][m] = av.y;
            As[k4 * 4 + 2][m] = av.z;
            As[k4 * 4 + 3][m] = av.w;
        }
        // load B tile
        {
            int kb = t >> 4, c4 = t & 15;
            *(float4*)&Bs[kb][c4 * 4] =
                *(const float4*)(B + (size_t)(kt + kb) * ldb + bn0 + c4 * 4);
        }
        __syncthreads();
#pragma unroll
        for (int kk = 0; kk < 16; kk++) {
            float4 b0 = *(float4*)&Bs[kk][col0];
            float4 a0 = *(float4*)&As[kk][row0];
            float4 a1 = *(float4*)&As[kk][row0 + 4];
            float aa[8] = {a0.x, a0.y, a0.z, a0.w, a1.x, a1.y, a1.z, a1.w};
            float bb[4] = {b0.x, b0.y, b0.z, b0.w};
#pragma unroll
            for (int i = 0; i < 8; i++)
#pragma unroll
                for (int j = 0; j < 4; j++) acc[i][j] += aa[i] * bb[j];
        }
        __syncthreads();
    }

    float add[4] = {0.f, 0.f, 0.f, 0.f};
    if (bias) {
#pragma unroll
        for (int j = 0; j < 4; j++) add[j] += bias[bn0 + col0 + j];
    }
    if (colsub) {
#pragma unroll
        for (int j = 0; j < 4; j++) add[j] -= colsub[bn0 + col0 + j];
    }
#pragma unroll
    for (int i = 0; i < 8; i++) {
        float4 v;
        v.x = alpha * acc[i][0] + add[0];
        v.y = alpha * acc[i][1] + add[1];
        v.z = alpha * acc[i][2] + add[2];
        v.w = alpha * acc[i][3] + add[3];
        if (RELU) {
            v.x = fmaxf(v.x, 0.f);
            v.y = fmaxf(v.y, 0.f);
            v.z = fmaxf(v.z, 0.f);
            v.w = fmaxf(v.w, 0.f);
        }
        *(float4*)(C + (size_t)(bm0 + row0 + i) * ldc + bn0 + col0) = v;
    }
}

// ---------------- column-wise (over queries) logsumexp of S = Q K^T / 8 ------------
// grid: (key_tiles=16, heads=16). 256 threads. Key tile 128 resident; stream 128-query
// chunks; online logsumexp per key. Dynamic smem.
#define LSE_SMEM_FLOATS (2 * 64 * 132 + 2 * 128 * 17 + 256)
__global__ void __launch_bounds__(256) lse_kernel(const float* __restrict__ Q,
                                                  const float* __restrict__ K,
                                                  float* __restrict__ lse) {
    extern __shared__ float sm[];
    float* Ks = sm;                 // [64][132] : Ks[d][m]
    float* Qs = Ks + 64 * 132;      // [64][132] : Qs[d][q]
    float* pm = Qs + 64 * 132;      // [128][17]
    float* ps = pm + 128 * 17;      // [128][17]
    float* Ms = ps + 128 * 17;      // [128]
    float* Ls = Ms + 128;           // [128]

    int h = blockIdx.y;
    int m0 = blockIdx.x * 128;
    const float* Kh = K + (size_t)h * N_ * DK_;
    const float* Qh = Q + (size_t)h * N_ * DK_;
    int t = threadIdx.x;

#pragma unroll
    for (int r = 0; r < 8; r++) {
        int f = t + 256 * r;
        int m = f >> 4, d4 = f & 15;
        float4 v = *(const float4*)(Kh + (size_t)(m0 + m) * DK_ + d4 * 4);
        Ks[(d4 * 4 + 0) * 132 + m] = v.x;
        Ks[(d4 * 4 + 1) * 132 + m] = v.y;
        Ks[(d4 * 4 + 2) * 132 + m] = v.z;
        Ks[(d4 * 4 + 3) * 132 + m] = v.w;
    }
    if (t < 128) { Ms[t] = -INFINITY; Ls[t] = 0.f; }
    __syncthreads();

    int ty = t >> 4, tx = t & 15;
    int row0 = ty * 8, col0 = tx * 8;

    for (int q0 = 0; q0 < N_; q0 += 128) {
#pragma unroll
        for (int r = 0; r < 8; r++) {
            int f = t + 256 * r;
            int m = f >> 4, d4 = f & 15;
            float4 v = *(const float4*)(Qh + (size_t)(q0 + m) * DK_ + d4 * 4);
            Qs[(d4 * 4 + 0) * 132 + m] = v.x;
            Qs[(d4 * 4 + 1) * 132 + m] = v.y;
            Qs[(d4 * 4 + 2) * 132 + m] = v.z;
            Qs[(d4 * 4 + 3) * 132 + m] = v.w;
        }
        __syncthreads();

        float c[8][8];
#pragma unroll
        for (int i = 0; i < 8; i++)
#pragma unroll
            for (int j = 0; j < 8; j++) c[i][j] = 0.f;

#pragma unroll 4
        for (int d = 0; d < 64; d++) {
            float4 a0 = *(float4*)&Qs[d * 132 + row0];
            float4 a1 = *(float4*)&Qs[d * 132 + row0 + 4];
            float4 b0 = *(float4*)&Ks[d * 132 + col0];
            float4 b1 = *(float4*)&Ks[d * 132 + col0 + 4];
            float aa[8] = {a0.x, a0.y, a0.z, a0.w, a1.x, a1.y, a1.z, a1.w};
            float bb[8] = {b0.x, b0.y, b0.z, b0.w, b1.x, b1.y, b1.z, b1.w};
#pragma unroll
            for (int i = 0; i < 8; i++)
#pragma unroll
                for (int j = 0; j < 8; j++) c[i][j] += aa[i] * bb[j];
        }

        // per-thread partial (over its 8 query rows) max & sumexp per key col
#pragma unroll
        for (int j = 0; j < 8; j++) {
            float mx = -INFINITY;
#pragma unroll
            for (int i = 0; i < 8; i++) mx = fmaxf(mx, c[i][j] * 0.125f);
            float s = 0.f;
#pragma unroll
            for (int i = 0; i < 8; i++) s += expf(c[i][j] * 0.125f - mx);
            pm[(col0 + j) * 17 + ty] = mx;
            ps[(col0 + j) * 17 + ty] = s;
        }
        __syncthreads();

        if (t < 128) {
            float M = Ms[t], Ll = Ls[t];
#pragma unroll
            for (int g = 0; g < 16; g++) {
                float m2 = fmaxf(M, pm[t * 17 + g]);
                Ll = Ll * expf(M - m2) + ps[t * 17 + g] * expf(pm[t * 17 + g] - m2);
                M = m2;
            }
            Ms[t] = M;
            Ls[t] = Ll;
        }
        __syncthreads();
    }

    if (t < 128) lse[(size_t)h * N_ + m0 + t] = Ms[t] + logf(Ls[t]);
}

// ---------------- KtV[h] = K[h]^T V[h] (64x64), lseV[h] = lse[h]^T V[h] ------------
__global__ void zero_ktv(float* __restrict__ KtV, float* __restrict__ lseV) {
    int i = blockIdx.x * 256 + threadIdx.x;
    if (i < H_ * DK_ * DV_) KtV[i] = 0.f;
    if (i < H_ * DV_) lseV[i] = 0.f;
}

__global__ void __launch_bounds__(256) ktv_kernel(const float* __restrict__ K,
                                                  const float* __restrict__ V,
                                                  const float* __restrict__ lse,
                                                  float* __restrict__ KtV,
                                                  float* __restrict__ lseV) {
    __shared__ float Ks[64][64];
    __shared__ float Vs[64][64];
    __shared__ float ls[64];
    int h = blockIdx.y;
    int k0 = blockIdx.x * 256;
    const float* Kh = K + (size_t)h * N_ * DK_;
    const float* Vh = V + (size_t)h * N_ * DV_;
    const float* lh = lse + (size_t)h * N_;
    int t = threadIdx.x;
    int ty = t >> 4, tx = t & 15;

    float c[4][4];
#pragma unroll
    for (int i = 0; i < 4; i++)
#pragma unroll
        for (int j = 0; j < 4; j++) c[i][j] = 0.f;
    float lv[4] = {0.f, 0.f, 0.f, 0.f};

    for (int kc = k0; kc < k0 + 256; kc += 64) {
#pragma unroll
        for (int r = 0; r < 4; r++) {
            int f = t + 256 * r;
            int row = f >> 4, c4 = f & 15;
            *(float4*)&Ks[row][c4 * 4] = *(const float4*)(Kh + (size_t)(kc + row) * DK_ + c4 * 4);
            *(float4*)&Vs[row][c4 * 4] = *(const float4*)(Vh + (size_t)(kc + row) * DV_ + c4 * 4);
        }
        if (t < 64) ls[t] = lh[kc + t];
        __syncthreads();
#pragma unroll 8
        for (int kk = 0; kk < 64; kk++) {
            float4 a = *(float4*)&Ks[kk][ty * 4];
            float4 b = *(float4*)&Vs[kk][tx * 4];
            float aa[4] = {a.x, a.y, a.z, a.w};
            float bb[4] = {b.x, b.y, b.z, b.w};
#pragma unroll
            for (int i = 0; i < 4; i++)
#pragma unroll
                for (int j = 0; j < 4; j++) c[i][j] += aa[i] * bb[j];
            if (ty == 0) {
                float l = ls[kk];
#pragma unroll
                for (int j = 0; j < 4; j++) lv[j] += l * bb[j];
            }
        }
        __syncthreads();
    }
#pragma unroll
    for (int i = 0; i < 4; i++)
#pragma unroll
        for (int j = 0; j < 4; j++)
            atomicAdd(&KtV[(size_t)h * DK_ * DV_ + (ty * 4 + i) * DV_ + tx * 4 + j], c[i][j]);
    if (ty == 0) {
#pragma unroll
        for (int j = 0; j < 4; j++) atomicAdd(&lseV[(size_t)h * DV_ + tx * 4 + j], lv[j]);
    }
}

// ---------------- layernorm (ddof=1): out = g/std*(x-mean)+be, x = a+b ----------------
__global__ void __launch_bounds__(256) ln_kernel(const float* __restrict__ a,
                                                 const float* __restrict__ b,
                                                 const float* __restrict__ g,
                                                 const float* __restrict__ be,
                                                 float* __restrict__ out) {
    __shared__ float red[256];
    int n = blockIdx.x;
    int t = threadIdx.x;
    size_t base = (size_t)n * DM_;
    float x[4];
    float s = 0.f;
#pragma unroll
    for (int k = 0; k < 4; k++) {
        int d = t + k * 256;
        x[k] = a[base + d] + b[base + d];
        s += x[k];
    }
    red[t] = s;
    __syncthreads();
    for (int o = 128; o > 0; o >>= 1) {
        if (t < o) red[t] += red[t + o];
        __syncthreads();
    }
    float mean = red[0] * (1.f / (float)DM_);
    __syncthreads();
    float s2 = 0.f;
#pragma unroll
    for (int k = 0; k < 4; k++) {
        float d = x[k] - mean;
        s2 += d * d;
    }
    red[t] = s2;
    __syncthreads();
    for (int o = 128; o > 0; o >>= 1) {
        if (t < o) red[t] += red[t + o];
        __syncthreads();
    }
    float var = red[0] * (1.f / (float)(DM_ - 1));
    float invstd = 1.f / sqrtf(var);
#pragma unroll
    for (int k = 0; k < 4; k++) {
        int d = t + k * 256;
        out[base + d] = g[base + d] * invstd * (x[k] - mean) + be[base + d];
    }
}

// ---------------- launch ----------------
extern "C" void kernel_launch(void* const* d_in, const int* in_sizes, int n_in,
                              void* d_out, int out_size) {
    (void)in_sizes; (void)n_in; (void)out_size;
    const int*   X   = (const int*)d_in[0];
    const float* emb = (const float*)d_in[1];
    const float* WQ  = (const float*)d_in[2];
    const float* bQ  = (const float*)d_in[3];
    const float* WK  = (const float*)d_in[4];
    const float* bK  = (const float*)d_in[5];
    const float* WV  = (const float*)d_in[6];
    const float* bV  = (const float*)d_in[7];
    const float* WO  = (const float*)d_in[8];
    const float* bO  = (const float*)d_in[9];
    const float* W1  = (const float*)d_in[10];
    const float* b1  = (const float*)d_in[11];
    const float* W2  = (const float*)d_in[12];
    const float* b2  = (const float*)d_in[13];
    const float* g1  = (const float*)d_in[14];
    const float* be1 = (const float*)d_in[15];
    const float* g2  = (const float*)d_in[16];
    const float* be2 = (const float*)d_in[17];
    float* out = (float*)d_out;

    float *h, *Q, *K, *V, *lse, *KtV, *lseV, *attn, *Z, *h2, *F1, *R;
    cudaGetSymbolAddress((void**)&h, g_h);
    cudaGetSymbolAddress((void**)&Q, g_Q);
    cudaGetSymbolAddress((void**)&K, g_K);
    cudaGetSymbolAddress((void**)&V, g_V);
    cudaGetSymbolAddress((void**)&lse, g_lse);
    cudaGetSymbolAddress((void**)&KtV, g_KtV);
    cudaGetSymbolAddress((void**)&lseV, g_lseV);
    cudaGetSymbolAddress((void**)&attn, g_attn);
    cudaGetSymbolAddress((void**)&Z, g_Z);
    cudaGetSymbolAddress((void**)&h2, g_h2);
    cudaGetSymbolAddress((void**)&F1, g_F1);
    cudaGetSymbolAddress((void**)&R, g_R);

    cudaFuncSetAttribute(lse_kernel, cudaFuncAttributeMaxDynamicSharedMemorySize,
                         LSE_SMEM_FLOATS * 4);

    embed_kernel<<<N_, 256>>>(X, emb, h);

    for (int l = 0; l < L_; l++) {
        const float* WQl = WQ + (size_t)l * H_ * DM_ * DK_;
        const float* WKl = WK + (size_t)l * H_ * DM_ * DK_;
        const float* WVl = WV + (size_t)l * H_ * DM_ * DV_;
        const float* bQl = bQ + (size_t)l * H_ * DK_;
        const float* bKl = bK + (size_t)l * H_ * DK_;
        const float* bVl = bV + (size_t)l * H_ * DV_;
        const float* WOl = WO + (size_t)l * (H_ * DV_) * DM_;
        const float* bOl = bO + (size_t)l * DM_;
        const float* W1l = W1 + (size_t)l * DM_ * DFF_;
        const float* b1l = b1 + (size_t)l * DFF_;
        const float* W2l = W2 + (size_t)l * DFF_ * DM_;
        const float* b2l = b2 + (size_t)l * DM_;
        const float* g1l = g1 + (size_t)l * N_ * DM_;
        const float* be1l = be1 + (size_t)l * N_ * DM_;
        const float* g2l = g2 + (size_t)l * N_ * DM_;
        const float* be2l = be2 + (size_t)l * N_ * DM_;

        // Q/K/V projections: batched over 16 heads
        sgemm_kernel<false><<<dim3(1, N_ / 128, H_), 256>>>(
            h, WQl, Q, bQl, nullptr, N_, DK_, DM_, DM_, DK_, DK_,
            0L, (long)DM_ * DK_, (long)N_ * DK_, (long)DK_, 0L, 1.f);
        sgemm_kernel<false><<<dim3(1, N_ / 128, H_), 256>>>(
            h, WKl, K, bKl, nullptr, N_, DK_, DM_, DM_, DK_, DK_,
            0L, (long)DM_ * DK_, (long)N_ * DK_, (long)DK_, 0L, 1.f);
        sgemm_kernel<false><<<dim3(1, N_ / 128, H_), 256>>>(
            h, WVl, V, bVl, nullptr, N_, DV_, DM_, DM_, DV_, DV_,
            0L, (long)DM_ * DV_, (long)N_ * DV_, (long)DV_, 0L, 1.f);

        // column-wise logsumexp of S (over query axis), per key
        lse_kernel<<<dim3(N_ / 128, H_), 256, LSE_SMEM_FLOATS * 4>>>(Q, K, lse);

        // KtV + lseV
        zero_ktv<<<(H_ * DK_ * DV_ + 255) / 256, 256>>>(KtV, lseV);
        ktv_kernel<<<dim3(N_ / 256, H_), 256>>>(K, V, lse, KtV, lseV);

        // attn[n, h*64+v] = Q[h] @ KtV[h] / 8 - lseV[h][v]
        sgemm_kernel<false><<<dim3(1, N_ / 128, H_), 256>>>(
            Q, KtV, attn, nullptr, lseV, N_, DV_, DK_, DK_, DV_, DM_,
            (long)N_ * DK_, (long)DK_ * DV_, (long)DV_, 0L, (long)DV_, 0.125f);

        // Z = attn @ WO + bO
        sgemm_kernel<false><<<dim3(DM_ / 64, N_ / 128, 1), 256>>>(
            attn, WOl, Z, bOl, nullptr, N_, DM_, DM_, DM_, DM_, DM_,
            0L, 0L, 0L, 0L, 0L, 1.f);

        // h2 = LN(h + Z)
        ln_kernel<<<N_, 256>>>(h, Z, g1l, be1l, h2);

        // F1 = relu(h2 @ W1 + b1)
        sgemm_kernel<true><<<dim3(DFF_ / 64, N_ / 128, 1), 256>>>(
            h2, W1l, F1, b1l, nullptr, N_, DFF_, DM_, DM_, DFF_, DFF_,
            0L, 0L, 0L, 0L, 0L, 1.f);

        // R = F1 @ W2 + b2
        sgemm_kernel<false><<<dim3(DM_ / 64, N_ / 128, 1), 256>>>(
            F1, W2l, R, b2l, nullptr, N_, DM_, DFF_, DFF_, DM_, DM_,
            0L, 0L, 0L, 0L, 0L, 1.f);

        // h = LN(h2 + R)   (last layer writes straight to output)
        ln_kernel<<<N_, 256>>>(h2, R, g2l, be2l, (l == L_ - 1) ? out : h);
    }
}

// round 7
// speedup vs baseline: 1.7654x; 1.7654x over previous
#include <cuda_runtime.h>
#include <cuda_bf16.h>
#include <math.h>
#include <stdint.h>

#define L_ 6
#define H_ 16
#define N_ 2048
#define DM_ 1024
#define DK_ 64
#define DV_ 64
#define DFF_ 4096
#define QSTR (H_ * DK_)   // 1024, interleaved Q/K/V row stride

// ---------------- helpers ----------------
__device__ __forceinline__ uint32_t smem_u32(const void* p) {
    uint32_t a;
    asm("{ .reg .u64 t; cvta.to.shared.u64 t, %1; cvt.u32.u64 %0, t; }" : "=r"(a) : "l"(p));
    return a;
}
#define CPA16(saddr, gptr) \
    asm volatile("cp.async.cg.shared.global [%0], [%1], 16;" :: "r"(saddr), "l"(gptr) : "memory")
#define CP_COMMIT() asm volatile("cp.async.commit_group;" ::: "memory")
#define CP_WAIT0()  asm volatile("cp.async.wait_group 0;" ::: "memory")
#define CP_WAIT1()  asm volatile("cp.async.wait_group 1;" ::: "memory")

__device__ __forceinline__ void mma16816(float* c, const uint32_t* a, const uint32_t* b) {
    asm volatile(
        "mma.sync.aligned.m16n8k16.row.col.f32.bf16.bf16.f32 "
        "{%0,%1,%2,%3}, {%4,%5,%6,%7}, {%8,%9}, {%0,%1,%2,%3};"
        : "+f"(c[0]), "+f"(c[1]), "+f"(c[2]), "+f"(c[3])
        : "r"(a[0]), "r"(a[1]), "r"(a[2]), "r"(a[3]), "r"(b[0]), "r"(b[1]));
}

// ---------------- scratch ----------------
__device__ float g_h[N_ * DM_];
__device__ float g_Q[N_ * QSTR];
__device__ float g_K[N_ * QSTR];
__device__ float g_V[N_ * QSTR];
__device__ float g_lse[H_ * N_];
__device__ float g_KtV[H_ * DK_ * DV_];
__device__ float g_lseV[H_ * DV_];
__device__ float g_attn[N_ * DM_];
__device__ float g_Z[N_ * DM_];
__device__ float g_h2[N_ * DM_];
__device__ float g_F1[N_ * DFF_];
__device__ float g_R[N_ * DM_];
__device__ __nv_bfloat16 g_hh[N_ * DM_], g_hl[N_ * DM_];
__device__ __nv_bfloat16 g_h2h[N_ * DM_], g_h2l[N_ * DM_];
__device__ __nv_bfloat16 g_ath[N_ * DM_], g_atl[N_ * DM_];
__device__ __nv_bfloat16 g_F1h[N_ * DFF_], g_F1l[N_ * DFF_];
__device__ __nv_bfloat16 g_Wth[DFF_ * DM_], g_Wtl[DFF_ * DM_];

// one shared extern dynamic smem symbol for ALL kernels
extern __shared__ char dynsm[];

// ---------------- embedding + positional encoding ----------------
__global__ void embed_kernel(const int* __restrict__ X, const float* __restrict__ emb,
                             float* __restrict__ h) {
    int n = blockIdx.x;
    int t = threadIdx.x;
    const float* e = emb + (size_t)X[n] * DM_;
    float pos = (float)(n + 1);
#pragma unroll
    for (int k = 0; k < 2; k++) {
        int i = t + k * 256;
        float a = (float)(2 * i) / (float)DM_ * -9.210340371976184f;
        float f = expf(a);
        float tt = pos * f;
        h[(size_t)n * DM_ + 2 * i]     = e[2 * i]     + sinf(tt);
        h[(size_t)n * DM_ + 2 * i + 1] = e[2 * i + 1] + cosf(tt);
    }
}

// ---------------- fp32 -> bf16 hi/lo split ----------------
__global__ void cvt_kernel(const float* __restrict__ in, __nv_bfloat16* __restrict__ oh,
                           __nv_bfloat16* __restrict__ ol, int n) {
    int i = blockIdx.x * 256 + threadIdx.x;
    if (i < n) {
        float a = in[i];
        __nv_bfloat16 h = __float2bfloat16(a);
        oh[i] = h;
        ol[i] = __float2bfloat16(a - __bfloat162float(h));
    }
}

// ---------------- batched transpose + split: in [B][K][Nb] -> out [B*Nb][K] -------
__global__ void cvtT_kernel(const float* __restrict__ in, __nv_bfloat16* __restrict__ oh,
                            __nv_bfloat16* __restrict__ ol, int K, int Nb) {
    __shared__ float tile[32][33];
    int b = blockIdx.z;
    int k0 = blockIdx.x * 32, n0 = blockIdx.y * 32;
    int tx = threadIdx.x, ty = threadIdx.y;
    const float* W = in + (size_t)b * K * Nb;
#pragma unroll
    for (int r = 0; r < 4; r++)
        tile[ty + 8 * r][tx] = W[(size_t)(k0 + ty + 8 * r) * Nb + n0 + tx];
    __syncthreads();
#pragma unroll
    for (int r = 0; r < 4; r++) {
        float a = tile[tx][ty + 8 * r];
        size_t o = (size_t)(b * Nb + n0 + ty + 8 * r) * K + k0 + tx;
        __nv_bfloat16 h = __float2bfloat16(a);
        oh[o] = h;
        ol[o] = __float2bfloat16(a - __bfloat162float(h));
    }
}

// ---------------- HMMA GEMM: C[M,N] = A[M,K] @ Bt[N,K]^T + bias, opt relu ---------
// hi/lo split: C = Ah*Bh + Ah*Bl + Al*Bh (fp32 accum via mma.sync m16n8k16 bf16)
// 256 thr = 8 warps (4m x 2n); warp tile 32x64; BK=32; cp.async double buffer.
#define BM 128
#define BN 128
#define BK 32
#define KP 40                          // padded row stride in bf16 elems (80B)
#define MAT_ELE (BM * KP)              // per-matrix smem elems
#define STAGE_ELE (4 * MAT_ELE)        // Ah,Al,Bh,Bl
#define HG_SMEM (2 * STAGE_ELE * 2)    // bytes = 81920
template <bool RELU>
__global__ void __launch_bounds__(256) hmma_gemm(
    const __nv_bfloat16* __restrict__ Ah, const __nv_bfloat16* __restrict__ Al,
    const __nv_bfloat16* __restrict__ Bh, const __nv_bfloat16* __restrict__ Bl,
    float* __restrict__ C, const float* __restrict__ bias, int M, int N, int K) {
    __nv_bfloat16* smem = (__nv_bfloat16*)dynsm;
    uint32_t smb = smem_u32(dynsm);

    int t = threadIdx.x;
    int warp = t >> 5, lane = t & 31;
    int wm = warp & 3, wn = warp >> 2;
    int g = lane >> 2, tg = lane & 3;
    int bn0 = blockIdx.x * BN, bm0 = blockIdx.y * BM;

    const __nv_bfloat16* srcs[4] = {Ah, Al, Bh, Bl};
    int rowbase[4] = {bm0, bm0, bn0, bn0};

    float acc[2][8][4];
#pragma unroll
    for (int i = 0; i < 2; i++)
#pragma unroll
        for (int j = 0; j < 8; j++)
#pragma unroll
            for (int k = 0; k < 4; k++) acc[i][j][k] = 0.f;

    const int nch = K / BK;

    // cp.async issue of chunk c into buffer c&1: 8 x 16B per thread
    auto issue = [&](int c) {
        uint32_t sb = smb + (uint32_t)((c & 1) * STAGE_ELE * 2);
#pragma unroll
        for (int mt = 0; mt < 4; mt++) {
#pragma unroll
            for (int r = 0; r < 2; r++) {
                int f = t + 256 * r;        // < 512
                int m = f >> 2, ck = f & 3; // 4 chunks of 8 bf16 per 32-k row
                const __nv_bfloat16* gp =
                    srcs[mt] + (size_t)(rowbase[mt] + m) * K + c * BK + ck * 8;
                uint32_t sa = sb + (uint32_t)((mt * MAT_ELE + m * KP + ck * 8) * 2);
                CPA16(sa, gp);
            }
        }
    };

    issue(0);
    CP_COMMIT();

    for (int c = 0; c < nch; c++) {
        if (c + 1 < nch) {
            issue(c + 1);
            CP_COMMIT();
            CP_WAIT1();
        } else {
            CP_WAIT0();
        }
        __syncthreads();

        const __nv_bfloat16* cur = smem + (c & 1) * STAGE_ELE;
        const __nv_bfloat16* As_h = cur;
        const __nv_bfloat16* As_l = cur + MAT_ELE;
        const __nv_bfloat16* Bs_h = cur + 2 * MAT_ELE;
        const __nv_bfloat16* Bs_l = cur + 3 * MAT_ELE;

#pragma unroll
        for (int ks = 0; ks < 2; ks++) {
            int k0 = ks * 16 + tg * 2;
            uint32_t ah[2][4], al[2][4];
#pragma unroll
            for (int mt = 0; mt < 2; mt++) {
                int row = wm * 32 + mt * 16;
                ah[mt][0] = *(const uint32_t*)&As_h[(row + g) * KP + k0];
                ah[mt][1] = *(const uint32_t*)&As_h[(row + 8 + g) * KP + k0];
                ah[mt][2] = *(const uint32_t*)&As_h[(row + g) * KP + k0 + 8];
                ah[mt][3] = *(const uint32_t*)&As_h[(row + 8 + g) * KP + k0 + 8];
                al[mt][0] = *(const uint32_t*)&As_l[(row + g) * KP + k0];
                al[mt][1] = *(const uint32_t*)&As_l[(row + 8 + g) * KP + k0];
                al[mt][2] = *(const uint32_t*)&As_l[(row + g) * KP + k0 + 8];
                al[mt][3] = *(const uint32_t*)&As_l[(row + 8 + g) * KP + k0 + 8];
            }
#pragma unroll
            for (int nt = 0; nt < 8; nt++) {
                int rn = wn * 64 + nt * 8 + g;
                uint32_t bh[2], bl[2];
                bh[0] = *(const uint32_t*)&Bs_h[rn * KP + k0];
                bh[1] = *(const uint32_t*)&Bs_h[rn * KP + k0 + 8];
                bl[0] = *(const uint32_t*)&Bs_l[rn * KP + k0];
                bl[1] = *(const uint32_t*)&Bs_l[rn * KP + k0 + 8];
#pragma unroll
                for (int mt = 0; mt < 2; mt++) {
                    mma16816(acc[mt][nt], ah[mt], bh);
                    mma16816(acc[mt][nt], ah[mt], bl);
                    mma16816(acc[mt][nt], al[mt], bh);
                }
            }
        }
        __syncthreads();
    }

    // epilogue: c0,c1 -> (row+g, col+tg*2); c2,c3 -> (row+8+g, col+tg*2)
#pragma unroll
    for (int mt = 0; mt < 2; mt++) {
        int row = bm0 + wm * 32 + mt * 16;
#pragma unroll
        for (int nt = 0; nt < 8; nt++) {
            int coln = bn0 + wn * 64 + nt * 8 + tg * 2;
            float bx = bias[coln], by = bias[coln + 1];
            float v0 = acc[mt][nt][0] + bx;
            float v1 = acc[mt][nt][1] + by;
            float v2 = acc[mt][nt][2] + bx;
            float v3 = acc[mt][nt][3] + by;
            if (RELU) {
                v0 = fmaxf(v0, 0.f); v1 = fmaxf(v1, 0.f);
                v2 = fmaxf(v2, 0.f); v3 = fmaxf(v3, 0.f);
            }
            float2 p0 = {v0, v1}, p1 = {v2, v3};
            *(float2*)&C[(size_t)(row + g) * N + coln] = p0;
            *(float2*)&C[(size_t)(row + 8 + g) * N + coln] = p1;
        }
    }
}

// ---------------- column-wise (over queries) logsumexp of S = Q K^T / 8 ------------
#define LSE_SMEM_FLOATS (2 * 64 * 132 + 2 * 128 * 17 + 256)
__global__ void __launch_bounds__(256) lse_kernel(const float* __restrict__ Q,
                                                  const float* __restrict__ K,
                                                  float* __restrict__ lse) {
    float* sm = (float*)dynsm;
    float* Ks = sm;
    float* Qs = Ks + 64 * 132;
    float* pm = Qs + 64 * 132;
    float* ps = pm + 128 * 17;
    float* Ms = ps + 128 * 17;
    float* Ls = Ms + 128;

    int h = blockIdx.y;
    int m0 = blockIdx.x * 128;
    const float* Kh = K + h * 64;
    const float* Qh = Q + h * 64;
    int t = threadIdx.x;

#pragma unroll
    for (int r = 0; r < 8; r++) {
        int f = t + 256 * r;
        int m = f >> 4, d4 = f & 15;
        float4 v = *(const float4*)(Kh + (size_t)(m0 + m) * QSTR + d4 * 4);
        Ks[(d4 * 4 + 0) * 132 + m] = v.x;
        Ks[(d4 * 4 + 1) * 132 + m] = v.y;
        Ks[(d4 * 4 + 2) * 132 + m] = v.z;
        Ks[(d4 * 4 + 3) * 132 + m] = v.w;
    }
    if (t < 128) { Ms[t] = -INFINITY; Ls[t] = 0.f; }
    __syncthreads();

    int ty = t >> 4, tx = t & 15;
    int row0 = ty * 8, col0 = tx * 8;

    for (int q0 = 0; q0 < N_; q0 += 128) {
#pragma unroll
        for (int r = 0; r < 8; r++) {
            int f = t + 256 * r;
            int m = f >> 4, d4 = f & 15;
            float4 v = *(const float4*)(Qh + (size_t)(q0 + m) * QSTR + d4 * 4);
            Qs[(d4 * 4 + 0) * 132 + m] = v.x;
            Qs[(d4 * 4 + 1) * 132 + m] = v.y;
            Qs[(d4 * 4 + 2) * 132 + m] = v.z;
            Qs[(d4 * 4 + 3) * 132 + m] = v.w;
        }
        __syncthreads();

        float c[8][8];
#pragma unroll
        for (int i = 0; i < 8; i++)
#pragma unroll
            for (int j = 0; j < 8; j++) c[i][j] = 0.f;

#pragma unroll 4
        for (int d = 0; d < 64; d++) {
            float4 a0 = *(float4*)&Qs[d * 132 + row0];
            float4 a1 = *(float4*)&Qs[d * 132 + row0 + 4];
            float4 b0 = *(float4*)&Ks[d * 132 + col0];
            float4 b1 = *(float4*)&Ks[d * 132 + col0 + 4];
            float aa[8] = {a0.x, a0.y, a0.z, a0.w, a1.x, a1.y, a1.z, a1.w};
            float bb[8] = {b0.x, b0.y, b0.z, b0.w, b1.x, b1.y, b1.z, b1.w};
#pragma unroll
            for (int i = 0; i < 8; i++)
#pragma unroll
                for (int j = 0; j < 8; j++) c[i][j] += aa[i] * bb[j];
        }

#pragma unroll
        for (int j = 0; j < 8; j++) {
            float mx = -INFINITY;
#pragma unroll
            for (int i = 0; i < 8; i++) mx = fmaxf(mx, c[i][j] * 0.125f);
            float s = 0.f;
#pragma unroll
            for (int i = 0; i < 8; i++) s += expf(c[i][j] * 0.125f - mx);
            pm[(col0 + j) * 17 + ty] = mx;
            ps[(col0 + j) * 17 + ty] = s;
        }
        __syncthreads();

        if (t < 128) {
            float M = Ms[t], Ll = Ls[t];
#pragma unroll
            for (int g = 0; g < 16; g++) {
                float m2 = fmaxf(M, pm[t * 17 + g]);
                Ll = Ll * expf(M - m2) + ps[t * 17 + g] * expf(pm[t * 17 + g] - m2);
                M = m2;
            }
            Ms[t] = M;
            Ls[t] = Ll;
        }
        __syncthreads();
    }

    if (t < 128) lse[(size_t)h * N_ + m0 + t] = Ms[t] + logf(Ls[t]);
}

// ---------------- KtV[h] = K[h]^T V[h], lseV[h] = lse[h]^T V[h] ------------
__global__ void zero_ktv(float* __restrict__ KtV, float* __restrict__ lseV) {
    int i = blockIdx.x * 256 + threadIdx.x;
    if (i < H_ * DK_ * DV_) KtV[i] = 0.f;
    if (i < H_ * DV_) lseV[i] = 0.f;
}

__global__ void __launch_bounds__(256) ktv_kernel(const float* __restrict__ K,
                                                  const float* __restrict__ V,
                                                  const float* __restrict__ lse,
                                                  float* __restrict__ KtV,
                                                  float* __restrict__ lseV) {
    __shared__ float Ks[64][64];
    __shared__ float Vs[64][64];
    __shared__ float ls[64];
    int h = blockIdx.y;
    int k0 = blockIdx.x * 256;
    const float* Kh = K + h * 64;
    const float* Vh = V + h * 64;
    const float* lh = lse + (size_t)h * N_;
    int t = threadIdx.x;
    int ty = t >> 4, tx = t & 15;

    float c[4][4];
#pragma unroll
    for (int i = 0; i < 4; i++)
#pragma unroll
        for (int j = 0; j < 4; j++) c[i][j] = 0.f;
    float lv[4] = {0.f, 0.f, 0.f, 0.f};

    for (int kc = k0; kc < k0 + 256; kc += 64) {
#pragma unroll
        for (int r = 0; r < 4; r++) {
            int f = t + 256 * r;
            int row = f >> 4, c4 = f & 15;
            *(float4*)&Ks[row][c4 * 4] = *(const float4*)(Kh + (size_t)(kc + row) * QSTR + c4 * 4);
            *(float4*)&Vs[row][c4 * 4] = *(const float4*)(Vh + (size_t)(kc + row) * QSTR + c4 * 4);
        }
        if (t < 64) ls[t] = lh[kc + t];
        __syncthreads();
#pragma unroll 8
        for (int kk = 0; kk < 64; kk++) {
            float4 a = *(float4*)&Ks[kk][ty * 4];
            float4 b = *(float4*)&Vs[kk][tx * 4];
            float aa[4] = {a.x, a.y, a.z, a.w};
            float bb[4] = {b.x, b.y, b.z, b.w};
#pragma unroll
            for (int i = 0; i < 4; i++)
#pragma unroll
                for (int j = 0; j < 4; j++) c[i][j] += aa[i] * bb[j];
            if (ty == 0) {
                float l = ls[kk];
#pragma unroll
                for (int j = 0; j < 4; j++) lv[j] += l * bb[j];
            }
        }
        __syncthreads();
    }
#pragma unroll
    for (int i = 0; i < 4; i++)
#pragma unroll
        for (int j = 0; j < 4; j++)
            atomicAdd(&KtV[(size_t)h * DK_ * DV_ + (ty * 4 + i) * DV_ + tx * 4 + j], c[i][j]);
    if (ty == 0) {
#pragma unroll
        for (int j = 0; j < 4; j++) atomicAdd(&lseV[(size_t)h * DV_ + tx * 4 + j], lv[j]);
    }
}

// ---------------- SIMT sgemm (small per-head attn GEMM) ----------------
template <bool RELU>
__global__ void __launch_bounds__(256) sgemm_kernel(
    const float* __restrict__ A, const float* __restrict__ B, float* __restrict__ C,
    const float* __restrict__ bias, const float* __restrict__ colsub,
    int M, int Nc, int Kd, int lda, int ldb, int ldc,
    long sA, long sB, long sC, long sBias, long sSub, float alpha) {
    __shared__ float As[16][132];
    __shared__ float Bs[16][64];

    int b = blockIdx.z;
    A += (size_t)b * sA;
    B += (size_t)b * sB;
    C += (size_t)b * sC;
    if (bias) bias += (size_t)b * sBias;
    if (colsub) colsub += (size_t)b * sSub;

    int bm0 = blockIdx.y * 128;
    int bn0 = blockIdx.x * 64;
    int t = threadIdx.x;
    int row0 = (t >> 4) * 8;
    int col0 = (t & 15) * 4;

    float acc[8][4];
#pragma unroll
    for (int i = 0; i < 8; i++)
#pragma unroll
        for (int j = 0; j < 4; j++) acc[i][j] = 0.f;

    for (int kt = 0; kt < Kd; kt += 16) {
#pragma unroll
        for (int r = 0; r < 2; r++) {
            int f = t + 256 * r;
            int m = f >> 2, k4 = f & 3;
            float4 av = *(const float4*)(A + (size_t)(bm0 + m) * lda + kt + k4 * 4);
            As[k4 * 4 + 0][m] = av.x;
            As[k4 * 4 + 1][m] = av.y;
            As[k4 * 4 + 2][m] = av.z;
            As[k4 * 4 + 3][m] = av.w;
        }
        {
            int kb = t >> 4, c4 = t & 15;
            *(float4*)&Bs[kb][c4 * 4] =
                *(const float4*)(B + (size_t)(kt + kb) * ldb + bn0 + c4 * 4);
        }
        __syncthreads();
#pragma unroll
        for (int kk = 0; kk < 16; kk++) {
            float4 b0 = *(float4*)&Bs[kk][col0];
            float4 a0 = *(float4*)&As[kk][row0];
            float4 a1 = *(float4*)&As[kk][row0 + 4];
            float aa[8] = {a0.x, a0.y, a0.z, a0.w, a1.x, a1.y, a1.z, a1.w};
            float bb[4] = {b0.x, b0.y, b0.z, b0.w};
#pragma unroll
            for (int i = 0; i < 8; i++)
#pragma unroll
                for (int j = 0; j < 4; j++) acc[i][j] += aa[i] * bb[j];
        }
        __syncthreads();
    }

    float add[4] = {0.f, 0.f, 0.f, 0.f};
    if (bias) {
#pragma unroll
        for (int j = 0; j < 4; j++) add[j] += bias[bn0 + col0 + j];
    }
    if (colsub) {
#pragma unroll
        for (int j = 0; j < 4; j++) add[j] -= colsub[bn0 + col0 + j];
    }
#pragma unroll
    for (int i = 0; i < 8; i++) {
        float4 v;
        v.x = alpha * acc[i][0] + add[0];
        v.y = alpha * acc[i][1] + add[1];
        v.z = alpha * acc[i][2] + add[2];
        v.w = alpha * acc[i][3] + add[3];
        if (RELU) {
            v.x = fmaxf(v.x, 0.f); v.y = fmaxf(v.y, 0.f);
            v.z = fmaxf(v.z, 0.f); v.w = fmaxf(v.w, 0.f);
        }
        *(float4*)(C + (size_t)(bm0 + row0 + i) * ldc + bn0 + col0) = v;
    }
}

// ---------------- layernorm (ddof=1) with fused bf16 hi/lo output ----------------
__global__ void __launch_bounds__(256) ln_kernel(const float* __restrict__ a,
                                                 const float* __restrict__ b,
                                                 const float* __restrict__ g,
                                                 const float* __restrict__ be,
                                                 float* __restrict__ out,
                                                 __nv_bfloat16* __restrict__ oh,
                                                 __nv_bfloat16* __restrict__ ol) {
    __shared__ float red[256];
    int n = blockIdx.x;
    int t = threadIdx.x;
    size_t base = (size_t)n * DM_;
    float x[4];
    float s = 0.f;
#pragma unroll
    for (int k = 0; k < 4; k++) {
        int d = t + k * 256;
        x[k] = a[base + d] + b[base + d];
        s += x[k];
    }
    red[t] = s;
    __syncthreads();
    for (int o = 128; o > 0; o >>= 1) {
        if (t < o) red[t] += red[t + o];
        __syncthreads();
    }
    float mean = red[0] * (1.f / (float)DM_);
    __syncthreads();
    float s2 = 0.f;
#pragma unroll
    for (int k = 0; k < 4; k++) {
        float d = x[k] - mean;
        s2 += d * d;
    }
    red[t] = s2;
    __syncthreads();
    for (int o = 128; o > 0; o >>= 1) {
        if (t < o) red[t] += red[t + o];
        __syncthreads();
    }
    float var = red[0] * (1.f / (float)(DM_ - 1));
    float invstd = 1.f / sqrtf(var);
#pragma unroll
    for (int k = 0; k < 4; k++) {
        int d = t + k * 256;
        float v = g[base + d] * invstd * (x[k] - mean) + be[base + d];
        out[base + d] = v;
        if (oh) {
            __nv_bfloat16 hv = __float2bfloat16(v);
            oh[base + d] = hv;
            ol[base + d] = __float2bfloat16(v - __bfloat162float(hv));
        }
    }
}

// ---------------- launch ----------------
extern "C" void kernel_launch(void* const* d_in, const int* in_sizes, int n_in,
                              void* d_out, int out_size) {
    (void)in_sizes; (void)n_in; (void)out_size;
    const int*   X   = (const int*)d_in[0];
    const float* emb = (const float*)d_in[1];
    const float* WQ  = (const float*)d_in[2];
    const float* bQ  = (const float*)d_in[3];
    const float* WK  = (const float*)d_in[4];
    const float* bK  = (const float*)d_in[5];
    const float* WV  = (const float*)d_in[6];
    const float* bV  = (const float*)d_in[7];
    const float* WO  = (const float*)d_in[8];
    const float* bO  = (const float*)d_in[9];
    const float* W1  = (const float*)d_in[10];
    const float* b1  = (const float*)d_in[11];
    const float* W2  = (const float*)d_in[12];
    const float* b2  = (const float*)d_in[13];
    const float* g1  = (const float*)d_in[14];
    const float* be1 = (const float*)d_in[15];
    const float* g2  = (const float*)d_in[16];
    const float* be2 = (const float*)d_in[17];
    float* out = (float*)d_out;

    float *h, *Q, *K, *V, *lse, *KtV, *lseV, *attn, *Z, *h2, *F1, *R;
    __nv_bfloat16 *hh, *hl, *h2h, *h2l, *ath, *atl, *F1h, *F1l, *Wth, *Wtl;
    cudaGetSymbolAddress((void**)&h, g_h);
    cudaGetSymbolAddress((void**)&Q, g_Q);
    cudaGetSymbolAddress((void**)&K, g_K);
    cudaGetSymbolAddress((void**)&V, g_V);
    cudaGetSymbolAddress((void**)&lse, g_lse);
    cudaGetSymbolAddress((void**)&KtV, g_KtV);
    cudaGetSymbolAddress((void**)&lseV, g_lseV);
    cudaGetSymbolAddress((void**)&attn, g_attn);
    cudaGetSymbolAddress((void**)&Z, g_Z);
    cudaGetSymbolAddress((void**)&h2, g_h2);
    cudaGetSymbolAddress((void**)&F1, g_F1);
    cudaGetSymbolAddress((void**)&R, g_R);
    cudaGetSymbolAddress((void**)&hh, g_hh);
    cudaGetSymbolAddress((void**)&hl, g_hl);
    cudaGetSymbolAddress((void**)&h2h, g_h2h);
    cudaGetSymbolAddress((void**)&h2l, g_h2l);
    cudaGetSymbolAddress((void**)&ath, g_ath);
    cudaGetSymbolAddress((void**)&atl, g_atl);
    cudaGetSymbolAddress((void**)&F1h, g_F1h);
    cudaGetSymbolAddress((void**)&F1l, g_F1l);
    cudaGetSymbolAddress((void**)&Wth, g_Wth);
    cudaGetSymbolAddress((void**)&Wtl, g_Wtl);

    cudaFuncSetAttribute(lse_kernel, cudaFuncAttributeMaxDynamicSharedMemorySize,
                         LSE_SMEM_FLOATS * 4);
    cudaFuncSetAttribute(hmma_gemm<false>, cudaFuncAttributeMaxDynamicSharedMemorySize, HG_SMEM);
    cudaFuncSetAttribute(hmma_gemm<true>, cudaFuncAttributeMaxDynamicSharedMemorySize, HG_SMEM);

    embed_kernel<<<N_, 256>>>(X, emb, h);
    cvt_kernel<<<(N_ * DM_ + 255) / 256, 256>>>(h, hh, hl, N_ * DM_);

    for (int l = 0; l < L_; l++) {
        const float* WQl = WQ + (size_t)l * H_ * DM_ * DK_;
        const float* WKl = WK + (size_t)l * H_ * DM_ * DK_;
        const float* WVl = WV + (size_t)l * H_ * DM_ * DV_;
        const float* bQl = bQ + (size_t)l * H_ * DK_;
        const float* bKl = bK + (size_t)l * H_ * DK_;
        const float* bVl = bV + (size_t)l * H_ * DV_;
        const float* WOl = WO + (size_t)l * (H_ * DV_) * DM_;
        const float* bOl = bO + (size_t)l * DM_;
        const float* W1l = W1 + (size_t)l * DM_ * DFF_;
        const float* b1l = b1 + (size_t)l * DFF_;
        const float* W2l = W2 + (size_t)l * DFF_ * DM_;
        const float* b2l = b2 + (size_t)l * DM_;
        const float* g1l = g1 + (size_t)l * N_ * DM_;
        const float* be1l = be1 + (size_t)l * N_ * DM_;
        const float* g2l = g2 + (size_t)l * N_ * DM_;
        const float* be2l = be2 + (size_t)l * N_ * DM_;

        // ---- Q/K/V: transpose-convert weights then one HMMA GEMM each
        cvtT_kernel<<<dim3(DM_ / 32, DK_ / 32, H_), dim3(32, 8)>>>(WQl, Wth, Wtl, DM_, DK_);
        hmma_gemm<false><<<dim3(QSTR / 128, N_ / 128), 256, HG_SMEM>>>(
            hh, hl, Wth, Wtl, Q, bQl, N_, QSTR, DM_);
        cvtT_kernel<<<dim3(DM_ / 32, DK_ / 32, H_), dim3(32, 8)>>>(WKl, Wth, Wtl, DM_, DK_);
        hmma_gemm<false><<<dim3(QSTR / 128, N_ / 128), 256, HG_SMEM>>>(
            hh, hl, Wth, Wtl, K, bKl, N_, QSTR, DM_);
        cvtT_kernel<<<dim3(DM_ / 32, DV_ / 32, H_), dim3(32, 8)>>>(WVl, Wth, Wtl, DM_, DV_);
        hmma_gemm<false><<<dim3(QSTR / 128, N_ / 128), 256, HG_SMEM>>>(
            hh, hl, Wth, Wtl, V, bVl, N_, QSTR, DM_);

        // ---- attention (restructured): lse over queries, then Q@(K^T V)/8 - lse^T V
        lse_kernel<<<dim3(N_ / 128, H_), 256, LSE_SMEM_FLOATS * 4>>>(Q, K, lse);
        zero_ktv<<<(H_ * DK_ * DV_ + 255) / 256, 256>>>(KtV, lseV);
        ktv_kernel<<<dim3(N_ / 256, H_), 256>>>(K, V, lse, KtV, lseV);
        sgemm_kernel<false><<<dim3(1, N_ / 128, H_), 256>>>(
            Q, KtV, attn, nullptr, lseV, N_, DV_, DK_, QSTR, DV_, DM_,
            64L, (long)DK_ * DV_, 64L, 0L, (long)DV_, 0.125f);
        cvt_kernel<<<(N_ * DM_ + 255) / 256, 256>>>(attn, ath, atl, N_ * DM_);

        // ---- Z = attn @ WO + bO
        cvtT_kernel<<<dim3((H_ * DV_) / 32, DM_ / 32, 1), dim3(32, 8)>>>(WOl, Wth, Wtl,
                                                                         H_ * DV_, DM_);
        hmma_gemm<false><<<dim3(DM_ / 128, N_ / 128), 256, HG_SMEM>>>(
            ath, atl, Wth, Wtl, Z, bOl, N_, DM_, DM_);

        // ---- h2 = LN(h + Z)
        ln_kernel<<<N_, 256>>>(h, Z, g1l, be1l, h2, h2h, h2l);

        // ---- F1 = relu(h2 @ W1 + b1)
        cvtT_kernel<<<dim3(DM_ / 32, DFF_ / 32, 1), dim3(32, 8)>>>(W1l, Wth, Wtl, DM_, DFF_);
        hmma_gemm<true><<<dim3(DFF_ / 128, N_ / 128), 256, HG_SMEM>>>(
            h2h, h2l, Wth, Wtl, F1, b1l, N_, DFF_, DM_);
        cvt_kernel<<<(N_ * DFF_ + 255) / 256, 256>>>(F1, F1h, F1l, N_ * DFF_);

        // ---- R = F1 @ W2 + b2
        cvtT_kernel<<<dim3(DFF_ / 32, DM_ / 32, 1), dim3(32, 8)>>>(W2l, Wth, Wtl, DFF_, DM_);
        hmma_gemm<false><<<dim3(DM_ / 128, N_ / 128), 256, HG_SMEM>>>(
            F1h, F1l, Wth, Wtl, R, b2l, N_, DM_, DFF_);

        // ---- h = LN(h2 + R)
        if (l == L_ - 1) {
            ln_kernel<<<N_, 256>>>(h2, R, g2l, be2l, out, nullptr, nullptr);
        } else {
            ln_kernel<<<N_, 256>>>(h2, R, g2l, be2l, h, hh, hl);
        }
    }
}